// round 10
// baseline (speedup 1.0000x reference)
#include <cuda_runtime.h>

// Shapes (fixed)
#define Bn 16
#define In 32
#define Cn 8
#define Jn 10
#define Dn 16
#define Xn 576   // D*H*W
#define XH 288
#define NT 288
#define HWn 36
#define EPSf 1e-7f
#define GRIDA (Bn*Jn*2)  // 320 CTAs for the loader (no barrier; waves pipeline)
#define GRIDB (Bn*Jn)    // 160 CTAs for routing (2/SM co-residency, 113 regs)

// Scratch
__device__ float    g_U[(size_t)Bn*Jn*In*Xn];    // [bj][i][x], 11.8 MB (L2-resident)
__device__ float    g_nPartH[GRIDA];             // iter-1 norm partials [bj*2+half]
__device__ float    g_aPartH[(size_t)GRIDA*In];  // iter-1 agreement [entry][i] 128B rows
__device__ float    g_nPart[2][GRIDB];           // kB norm buffers (parity)
__device__ float    g_aPart[2][GRIDB*In];        // kB agreement buffers [entry][i]
__device__ unsigned g_cnt;
__device__ unsigned g_gen;

__device__ __forceinline__ float squash_k(float n) {
    float n2 = n * n;
    return (n2 / (1.f + n2)) / (n + EPSf);
}

// Grid barrier (kB only: 160 CTAs, all co-resident at 2/SM).
__device__ __forceinline__ void gridBarrier() {
    __threadfence();
    __syncthreads();
    if (threadIdx.x == 0) {
        unsigned g0 = *(volatile unsigned*)&g_gen;
        unsigned a = atomicAdd(&g_cnt, 1u);
        if (a == GRIDB - 1) {
            atomicExch(&g_cnt, 0u);
            __threadfence();
            atomicAdd(&g_gen, 1u);
        } else {
            while (*(volatile unsigned*)&g_gen == g0) { }
        }
        __threadfence();
    }
    __syncthreads();
}

// Block sum over 288 threads; valid on thread 0.
__device__ __forceinline__ float blockReduceSum288(float v) {
    __shared__ float red[9];
    int lane = threadIdx.x & 31, w = threadIdx.x >> 5;
    #pragma unroll
    for (int o = 16; o > 0; o >>= 1) v += __shfl_down_sync(0xffffffffu, v, o);
    if (lane == 0) red[w] = v;
    __syncthreads();
    float s = 0.f;
    if (threadIdx.x == 0) {
        #pragma unroll
        for (int k = 0; k < 9; k++) s += red[k];
    }
    return s;
}

// ---------------------------------------------------------------------------
// Kernel A (R6-measured 14us @ 6.7TB/s): stream u_hat once, write U to gmem
// (stays in L2), fuse iteration-1 s / norm / agreement partials (c1 = 1/J).
// grid = 320 (bj, half), block = 288, registers uncapped, no barrier.
__global__ void __launch_bounds__(NT) k_load(const float* __restrict__ u,
                                             const float* __restrict__ bias) {
    __shared__ __align__(16) float Us[In][XH];
    __shared__ float ss[XH];
    int bj = blockIdx.x >> 1, half = blockIdx.x & 1;
    int b = bj / Jn, j = bj % Jn;
    int x = threadIdx.x;
    int xg = half * XH + x;
    int w = x >> 5, lane = x & 31;

    int t4 = x % 72, g = x / 72;              // 4 i-groups x 72 float4-cols
    int xq = half * XH + t4 * 4;
    const float* base = u + (size_t)b * In * Cn * Jn * Xn + (size_t)j * Xn + xq;
    float* uout = &g_U[(size_t)bj * In * Xn + xq];
    #pragma unroll 2
    for (int ii = 0; ii < 8; ii++) {
        int i = g * 8 + ii;
        const float4* p = (const float4*)(base + (size_t)i * Cn * Jn * Xn);
        float4 a0 = __ldcs(p);
        float4 a1 = __ldcs(p + 1 * (Jn * Xn / 4));
        float4 a2 = __ldcs(p + 2 * (Jn * Xn / 4));
        float4 a3 = __ldcs(p + 3 * (Jn * Xn / 4));
        float4 a4 = __ldcs(p + 4 * (Jn * Xn / 4));
        float4 a5 = __ldcs(p + 5 * (Jn * Xn / 4));
        float4 a6 = __ldcs(p + 6 * (Jn * Xn / 4));
        float4 a7 = __ldcs(p + 7 * (Jn * Xn / 4));
        float4 acc;
        acc.x = ((a0.x + a1.x) + (a2.x + a3.x)) + ((a4.x + a5.x) + (a6.x + a7.x));
        acc.y = ((a0.y + a1.y) + (a2.y + a3.y)) + ((a4.y + a5.y) + (a6.y + a7.y));
        acc.z = ((a0.z + a1.z) + (a2.z + a3.z)) + ((a4.z + a5.z) + (a6.z + a7.z));
        acc.w = ((a0.w + a1.w) + (a2.w + a3.w)) + ((a4.w + a5.w) + (a6.w + a7.w));
        *(float4*)&Us[i][t4 * 4] = acc;
        *(float4*)(uout + (size_t)i * Xn) = acc;   // plain store -> L2
    }
    __syncthreads();

    float acc = 0.f;
    #pragma unroll
    for (int i = 0; i < In; i++) acc += Us[i][x];
    float s = acc * (1.0f / Jn) + bias[j * Dn + xg / HWn];

    float n = blockReduceSum288(fabsf(s));
    if (x == 0) g_nPartH[blockIdx.x] = n;

    ss[x] = s;
    __syncthreads();
    if (w < 8) {
        #pragma unroll
        for (int ii = 0; ii < 4; ii++) {
            int i = w * 4 + ii;
            float a = 0.f;
            #pragma unroll
            for (int xx = lane; xx < XH; xx += 32) a += Us[i][xx] * ss[xx];
            #pragma unroll
            for (int o = 16; o > 0; o >>= 1) a += __shfl_down_sync(0xffffffffu, a, o);
            if (lane == 0) g_aPartH[(size_t)blockIdx.x * In + i] = a;
        }
    }
}

// ---------------------------------------------------------------------------
// Kernel B: reload U (72KB/CTA) via cp.async (no reg pressure, deep MLP,
// L2-hot), run iterations 2-3 with coalesced routing updates, 2 grid barriers,
// write output. grid = 160, block = 288, 2 CTAs/SM.
__global__ void __launch_bounds__(NT, 2) k_rest(const float* __restrict__ bias,
                                                float* __restrict__ out) {
    extern __shared__ __align__(16) float Us[];   // Us[i*Xn + x], 73,728 B
    __shared__ float ss[Xn];
    __shared__ float sb[In * Jn];
    __shared__ float cs[In];
    __shared__ float kb_sh[Bn];
    int bj = blockIdx.x;
    int b = bj / Jn, j = bj % Jn;
    int x = threadIdx.x;
    int w = x >> 5, lane = x & 31;
    float bias0 = bias[j * Dn + x / HWn];
    float bias1 = bias[j * Dn + (x + NT) / HWn];

    // ---- U reload via cp.async: 16 x 16B per thread, fully coalesced waves.
    {
        const char* gsrc = (const char*)&g_U[(size_t)bj * In * Xn];
        unsigned smem_base = (unsigned)__cvta_generic_to_shared(Us);
        #pragma unroll
        for (int k = 0; k < 16; k++) {
            int off = (k * NT + x) * 16;
            asm volatile("cp.async.cg.shared.global [%0], [%1], 16;\n"
                         :: "r"(smem_base + off), "l"(gsrc + off) : "memory");
        }
        asm volatile("cp.async.commit_group;\n" ::: "memory");
    }
    for (int t = x; t < In * Jn; t += NT) sb[t] = 0.f;
    asm volatile("cp.async.wait_group 0;\n" ::: "memory");
    __syncthreads();

    float s0 = 0.f, s1 = 0.f;
    #pragma unroll 1
    for (int iter = 1; iter < 3; iter++) {
        // ---- routing update from previous iteration's partials.
        if (iter == 1) {
            // partials from kernel A: [bj*2+half] layout
            if (x < Bn) {
                float nn = 0.f;
                #pragma unroll
                for (int t = 0; t < Jn * 2; t++) nn += __ldcg(&g_nPartH[x * Jn * 2 + t]);
                kb_sh[x] = squash_k(nn);
            }
            __syncthreads();
            for (int jj = w; jj < Jn; jj += 9) {
                float a = 0.f;
                #pragma unroll
                for (int bb = 0; bb < Bn; bb++) {
                    int e0 = (bb * Jn + jj) * 2;
                    a += kb_sh[bb] * (__ldcg(&g_aPartH[(size_t)e0 * In + lane])
                                    + __ldcg(&g_aPartH[(size_t)(e0 + 1) * In + lane]));
                }
                sb[lane * Jn + jj] += a;
            }
        } else {
            // partials from kB iter 1 (buffer 1)
            if (x < Bn) {
                float nn = 0.f;
                #pragma unroll
                for (int t = 0; t < Jn; t++) nn += __ldcg(&g_nPart[1][x * Jn + t]);
                kb_sh[x] = squash_k(nn);
            }
            __syncthreads();
            for (int jj = w; jj < Jn; jj += 9) {
                float a = 0.f;
                #pragma unroll
                for (int bb = 0; bb < Bn; bb++) {
                    int ent = bb * Jn + jj;
                    a += kb_sh[bb] * __ldcg(&g_aPart[1][(size_t)ent * In + lane]);
                }
                sb[lane * Jn + jj] += a;
            }
        }
        __syncthreads();
        if (x < In) {
            float mx = -1e30f;
            #pragma unroll
            for (int jj = 0; jj < Jn; jj++) mx = fmaxf(mx, sb[x * Jn + jj]);
            float den = 0.f;
            #pragma unroll
            for (int jj = 0; jj < Jn; jj++) den += expf(sb[x * Jn + jj] - mx);
            cs[x] = expf(sb[x * Jn + j] - mx) / den;
        }
        __syncthreads();

        // ---- s for this iteration (thread owns x and x+288)
        float a0 = 0.f, a1 = 0.f;
        #pragma unroll
        for (int i = 0; i < In; i++) {
            float c = cs[i];
            a0 += c * Us[i * Xn + x];
            a1 += c * Us[i * Xn + x + NT];
        }
        s0 = a0 + bias0;
        s1 = a1 + bias1;

        float n = blockReduceSum288(fabsf(s0) + fabsf(s1));
        if (x == 0) g_nPart[iter & 1][bj] = n;   // iter1->buf1, iter2->buf0

        if (iter == 2) break;                     // final agreement is dead

        ss[x] = s0;
        ss[x + NT] = s1;
        __syncthreads();
        if (w < 8) {
            #pragma unroll
            for (int ii = 0; ii < 4; ii++) {
                int i = w * 4 + ii;
                float a = 0.f;
                #pragma unroll
                for (int xx = lane; xx < Xn; xx += 32) a += Us[i * Xn + xx] * ss[xx];
                #pragma unroll
                for (int o = 16; o > 0; o >>= 1) a += __shfl_down_sync(0xffffffffu, a, o);
                if (lane == 0) g_aPart[1][(size_t)bj * In + i] = a;
            }
        }
        gridBarrier();
    }

    // ---- final squash (iter-2 norms in buffer 0)
    gridBarrier();
    if (x == 0) {
        float nn = 0.f;
        #pragma unroll
        for (int t = 0; t < Jn; t++) nn += __ldcg(&g_nPart[0][b * Jn + t]);
        kb_sh[0] = squash_k(nn);
    }
    __syncthreads();
    float kb = kb_sh[0];
    out[(size_t)bj * Xn + x]      = kb * s0;
    out[(size_t)bj * Xn + x + NT] = kb * s1;
}

extern "C" void kernel_launch(void* const* d_in, const int* in_sizes, int n_in,
                              void* d_out, int out_size) {
    const float* u    = (const float*)d_in[0];
    const float* bias = (const float*)d_in[1];
    float* out = (float*)d_out;
    const int dyn_smem = In * Xn * sizeof(float);   // 73,728 B
    cudaFuncSetAttribute(k_rest,
                         cudaFuncAttributeMaxDynamicSharedMemorySize, dyn_smem);
    k_load<<<GRIDA, NT>>>(u, bias);
    k_rest<<<GRIDB, NT, dyn_smem>>>(bias, out);
}